// round 14
// baseline (speedup 1.0000x reference)
#include <cuda_runtime.h>
#include <cuda_bf16.h>
#include <cstdint>
#include <cstddef>

typedef unsigned long long u64;

// Problem shape (fixed): B=128, S=1024, D=256, H=256
#define NB 128
#define NS 1024
#define NDIM 256
#define NH 256
#define G3 768              // 3*H

// gx scratch: [b][t][gate*256+h]  (402 MB, static device allocation — allowed)
__device__ float g_gx[(size_t)NB * NS * G3];

// ---------------- f32x2 helpers (sm_103a packed fp32) ----------------
__device__ __forceinline__ u64 pk2(float x, float y) {
    u64 r; asm("mov.b64 %0, {%1, %2};" : "=l"(r) : "f"(x), "f"(y)); return r;
}
__device__ __forceinline__ float2 up2(u64 a) {
    float2 r; asm("mov.b64 {%0, %1}, %2;" : "=f"(r.x), "=f"(r.y) : "l"(a)); return r;
}
__device__ __forceinline__ u64 ffma2(u64 a, u64 b, u64 c) {
    u64 d; asm("fma.rn.f32x2 %0, %1, %2, %3;" : "=l"(d) : "l"(a), "l"(b), "l"(c)); return d;
}
__device__ __forceinline__ float tanh_fast(float x) {
    float r; asm("tanh.approx.f32 %0, %1;" : "=f"(r) : "f"(x)); return r;
}
__device__ __forceinline__ float sigm_fast(float x) {
    // sigmoid(x) = 0.5 * tanh(x/2) + 0.5
    return fmaf(0.5f, tanh_fast(0.5f * x), 0.5f);
}

__device__ __forceinline__ unsigned smem_u32(const void* p) {
    unsigned a;
    asm("{ .reg .u64 t; cvta.to.shared.u64 t, %1; cvt.u32.u64 %0, t; }" : "=r"(a) : "l"(p));
    return a;
}
__device__ __forceinline__ unsigned mapa_rank(unsigned local, int rank) {
    unsigned r;
    asm("mapa.shared::cluster.u32 %0, %1, %2;" : "=r"(r) : "r"(local), "r"(rank));
    return r;
}
#define CLUSTER_SYNC() do { \
    asm volatile("barrier.cluster.arrive.aligned;" ::: "memory"); \
    asm volatile("barrier.cluster.wait.aligned;"   ::: "memory"); \
} while (0)

__device__ __forceinline__ void mbar_init(unsigned addr, unsigned cnt) {
    asm volatile("mbarrier.init.shared.b64 [%0], %1;" :: "r"(addr), "r"(cnt) : "memory");
}
__device__ __forceinline__ void mbar_expect_tx(unsigned addr, unsigned bytes) {
    asm volatile("mbarrier.arrive.expect_tx.shared.b64 _, [%0], %1;"
                 :: "r"(addr), "r"(bytes) : "memory");
}
__device__ __forceinline__ void mbar_wait(unsigned addr, unsigned parity) {
    asm volatile(
        "{\n\t"
        ".reg .pred P;\n\t"
        "WAIT_%=:\n\t"
        "mbarrier.try_wait.parity.acquire.cta.shared::cta.b64 P, [%0], %1, 0x989680;\n\t"
        "@P bra DONE_%=;\n\t"
        "bra WAIT_%=;\n\t"
        "DONE_%=:\n\t"
        "}"
        :: "r"(addr), "r"(parity) : "memory");
}
// remote smem store that completes tx on the remote CTA's mbarrier
__device__ __forceinline__ void st_async_tx(unsigned dst, unsigned val, unsigned rbar) {
    asm volatile(
        "st.async.weak.shared::cluster.mbarrier::complete_tx::bytes.b32 [%0], %1, [%2];"
        :: "r"(dst), "r"(val), "r"(rbar) : "memory");
}

// =====================================================================
// Phase 1: g_gx[m][n] = X[m][:] @ W_ih[:, n] + b_ih[n]
//   M = 131072 (m = b*1024 + t), K = 256, N = 768 (n = gate*256 + h)
// CTA tile 128x128, 256 threads, 8x8 per thread, f32x2 FMAs, KB=16.
// =====================================================================
#define KB1 16

__global__ void __launch_bounds__(256, 2)
gru_gemm1(const float* __restrict__ X, const float* __restrict__ W,
          const float* __restrict__ bias)
{
    __shared__ float As[KB1][132];   // [k][m], padded
    __shared__ float Bs[KB1][128];   // [k][n]

    const int tid   = threadIdx.x;
    const int mBase = blockIdx.y << 7;
    const int nBase = blockIdx.x << 7;
    const int tn = tid & 15;         // n sub-tile: tn*8
    const int tm = tid >> 4;         // m sub-tile: tm*8

    const int ar0 = tid >> 2;
    const int ac0 = (tid & 3) << 2;
    const int bk0 = tid >> 5;
    const int bn0 = (tid & 31) << 2;

    const float* Aptr = X + (size_t)(mBase + ar0) * NDIM + ac0;
    const float* Bptr = W + (size_t)bk0 * G3 + nBase + bn0;

    u64 acc[8][4];
#pragma unroll
    for (int i = 0; i < 8; ++i)
#pragma unroll
        for (int j = 0; j < 4; ++j) acc[i][j] = 0ull;

    float4 a0 = *(const float4*)(Aptr);
    float4 a1 = *(const float4*)(Aptr + 64 * NDIM);
    float4 b0 = *(const float4*)(Bptr);
    float4 b1 = *(const float4*)(Bptr + 8 * G3);

    for (int kc = 0; kc < NDIM; kc += KB1) {
        As[ac0 + 0][ar0] = a0.x; As[ac0 + 1][ar0] = a0.y;
        As[ac0 + 2][ar0] = a0.z; As[ac0 + 3][ar0] = a0.w;
        As[ac0 + 0][ar0 + 64] = a1.x; As[ac0 + 1][ar0 + 64] = a1.y;
        As[ac0 + 2][ar0 + 64] = a1.z; As[ac0 + 3][ar0 + 64] = a1.w;
        *(float4*)&Bs[bk0][bn0]     = b0;
        *(float4*)&Bs[bk0 + 8][bn0] = b1;
        __syncthreads();

        if (kc + KB1 < NDIM) {
            a0 = *(const float4*)(Aptr + (kc + KB1));
            a1 = *(const float4*)(Aptr + (kc + KB1) + 64 * NDIM);
            b0 = *(const float4*)(Bptr + (size_t)(kc + KB1) * G3);
            b1 = *(const float4*)(Bptr + (size_t)(kc + KB1 + 8) * G3);
        }

#pragma unroll
        for (int kk = 0; kk < KB1; ++kk) {
            float4 aA = *(const float4*)&As[kk][tm * 8];
            float4 aB = *(const float4*)&As[kk][tm * 8 + 4];
            u64 bp0 = *(const u64*)&Bs[kk][tn * 8 + 0];
            u64 bp1 = *(const u64*)&Bs[kk][tn * 8 + 2];
            u64 bp2 = *(const u64*)&Bs[kk][tn * 8 + 4];
            u64 bp3 = *(const u64*)&Bs[kk][tn * 8 + 6];
            u64 ad[8];
            ad[0] = pk2(aA.x, aA.x); ad[1] = pk2(aA.y, aA.y);
            ad[2] = pk2(aA.z, aA.z); ad[3] = pk2(aA.w, aA.w);
            ad[4] = pk2(aB.x, aB.x); ad[5] = pk2(aB.y, aB.y);
            ad[6] = pk2(aB.z, aB.z); ad[7] = pk2(aB.w, aB.w);
#pragma unroll
            for (int i = 0; i < 8; ++i) {
                acc[i][0] = ffma2(ad[i], bp0, acc[i][0]);
                acc[i][1] = ffma2(ad[i], bp1, acc[i][1]);
                acc[i][2] = ffma2(ad[i], bp2, acc[i][2]);
                acc[i][3] = ffma2(ad[i], bp3, acc[i][3]);
            }
        }
        __syncthreads();
    }

    float bb[8];
#pragma unroll
    for (int j = 0; j < 8; ++j) bb[j] = __ldg(bias + nBase + tn * 8 + j);

#pragma unroll
    for (int i = 0; i < 8; ++i) {
        size_t row = (size_t)(mBase + tm * 8 + i);
        float* o = g_gx + row * G3 + nBase + tn * 8;
        float2 p0 = up2(acc[i][0]), p1 = up2(acc[i][1]);
        float2 p2 = up2(acc[i][2]), p3 = up2(acc[i][3]);
        float4 lo = make_float4(p0.x + bb[0], p0.y + bb[1], p1.x + bb[2], p1.y + bb[3]);
        float4 hi = make_float4(p2.x + bb[4], p2.y + bb[5], p3.x + bb[6], p3.y + bb[7]);
        *(float4*)(o)     = lo;
        *(float4*)(o + 4) = hi;
    }
}

// =====================================================================
// Phase 2: GRU recurrence. 16 clusters x 8 CTAs; cluster = 8 batches;
// CTA = 32 hidden columns. 512 threads (16-way k-split).
// W_hh held in REGISTERS (48 floats/thread) — no W smem traffic in loop.
// Smem: hbuf[2][256][8] 16KB | part[16*8][100] 50KB | mbar[2]
// =====================================================================
#define HB_FLOATS   (2 * 256 * 8)           // 4096
#define PART_STRIDE 100                     // 3*32 + 4 pad (bank spread)
#define PART_FLOATS (16 * 8 * PART_STRIDE)  // 12800
#define HB_OFF_B    0
#define PART_OFF    HB_FLOATS
#define BAR_OFF_B   ((HB_FLOATS + PART_FLOATS) * 4)   // 67584
#define SMEM2_BYTES (BAR_OFF_B + 16)
#define TX_BYTES    8192u                   // 8 CTAs x 256 floats x 4B per step

__global__ void __launch_bounds__(512, 1) __cluster_dims__(8, 1, 1)
gru_rec(const float* __restrict__ mask, const float* __restrict__ Whh,
        const float* __restrict__ bhh, float* __restrict__ out)
{
    extern __shared__ float smem[];
    float* hbuf = smem;                  // [buf][k][lb]  (k = global h index)
    float* part = smem + PART_OFF;       // [(ks*8+lb)*100 + g*32 + hc]

    const int tid  = threadIdx.x;
    const int rank = blockIdx.x & 7;
    const int cid  = blockIdx.x >> 3;
    const int hc   = tid & 31;                  // k-loop lane role
    const int ks   = tid >> 5;                  // 0..15 (k-split warp)
    const int hcg  = rank * 32 + hc;
    // reduce-phase remap (tid < 256): lb fast, hc slow -> coalesced broadcast
    const int rlb  = tid & 7;
    const int rhc  = (tid >> 3) & 31;
    const int rhcg = rank * 32 + rhc;

    // ---- W_hh slice into REGISTERS: 16 k x 3 gates per thread ----
    float wrg[16], wzg[16], wng[16];
    {
        const float* wb = Whh + (size_t)(ks * 16) * G3 + hcg;
#pragma unroll
        for (int j = 0; j < 16; ++j) {
            wrg[j] = __ldg(wb + (size_t)j * G3 + 0);
            wzg[j] = __ldg(wb + (size_t)j * G3 + 256);
            wng[j] = __ldg(wb + (size_t)j * G3 + 512);
        }
    }
    for (int idx = tid; idx < HB_FLOATS; idx += 512) hbuf[idx] = 0.f;

    const unsigned smem_base = smem_u32(smem);
    const unsigned barL0 = smem_base + BAR_OFF_B;
    const unsigned barL1 = smem_base + BAR_OFF_B + 8;
    if (tid == 0) {
        mbar_init(barL0, 1);
        mbar_init(barL1, 1);
        mbar_expect_tx(barL0, TX_BYTES);
        mbar_expect_tx(barL1, TX_BYTES);
    }

    const float bhr = __ldg(bhh + 0 * 256 + rhcg);
    const float bhz = __ldg(bhh + 1 * 256 + rhcg);
    const float bhn = __ldg(bhh + 2 * 256 + rhcg);

    // remote smem bases for all 8 cluster ranks
    unsigned rbase[8];
#pragma unroll
    for (int r = 0; r < 8; ++r) rbase[r] = mapa_rank(smem_base, r);
    // this thread's h slot (same offset in every rank's hbuf): rank*256 + tid
    const unsigned slot_off = (unsigned)((rank * 256 + tid) * 4);

    const int b_glob = cid * 8 + rlb;
    size_t gxbase = (size_t)b_glob * NS * G3 + rhcg;
    size_t obase  = (size_t)b_glob * NS * NH + rhcg;
    size_t mbase  = (size_t)b_glob * NS;

    __syncthreads();
    CLUSTER_SYNC();   // barriers + zeroed hbuf visible cluster-wide

    unsigned p0 = 0, p1 = 0;   // per-buffer wait parity

    for (int t = 0; t < NS; ++t) {
        const int cur = t & 1;

        // prefetch gx + mask BEFORE the wait (independent of h)
        float gxr = 0.f, gxz = 0.f, gxn = 0.f, mv = 0.f;
        if (tid < 256) {
            gxr = __ldg(g_gx + gxbase + 0);
            gxz = __ldg(g_gx + gxbase + 256);
            gxn = __ldg(g_gx + gxbase + 512);
            mv  = __ldg(mask + mbase + t);
        }

        if (t > 0) {
            if (cur == 0) { mbar_wait(barL0, p0); p0 ^= 1; }
            else          { mbar_wait(barL1, p1); p1 ^= 1; }
            if (tid == 0 && t + 2 < NS)
                mbar_expect_tx(cur ? barL1 : barL0, TX_BYTES);
        }

        // ---- gh partial: 16 k x 8 batches x 3 gates; W in registers ----
        const float* hp = hbuf + cur * 2048 + ks * 128;
        u64 ar0 = 0, ar1 = 0, ar2 = 0, ar3 = 0;
        u64 az0 = 0, az1 = 0, az2 = 0, az3 = 0;
        u64 an0 = 0, an1 = 0, an2 = 0, an3 = 0;
#pragma unroll
        for (int kk = 0; kk < 16; ++kk) {
            ulonglong2 q0 = *(const ulonglong2*)(hp + kk * 8);
            ulonglong2 q1 = *(const ulonglong2*)(hp + kk * 8 + 4);
            u64 wr = pk2(wrg[kk], wrg[kk]);
            u64 wz = pk2(wzg[kk], wzg[kk]);
            u64 wn = pk2(wng[kk], wng[kk]);
            ar0 = ffma2(wr, q0.x, ar0); ar1 = ffma2(wr, q0.y, ar1);
            ar2 = ffma2(wr, q1.x, ar2); ar3 = ffma2(wr, q1.y, ar3);
            az0 = ffma2(wz, q0.x, az0); az1 = ffma2(wz, q0.y, az1);
            az2 = ffma2(wz, q1.x, az2); az3 = ffma2(wz, q1.y, az3);
            an0 = ffma2(wn, q0.x, an0); an1 = ffma2(wn, q0.y, an1);
            an2 = ffma2(wn, q1.x, an2); an3 = ffma2(wn, q1.y, an3);
        }
        {
            float2 v;
            float* pb = part + ks * 8 * PART_STRIDE + hc;
#define PW(G, LB0, V0, V1) \
            pb[(LB0) * PART_STRIDE + (G) * 32] = (V0); \
            pb[((LB0) + 1) * PART_STRIDE + (G) * 32] = (V1);
            v = up2(ar0); PW(0, 0, v.x, v.y)
            v = up2(ar1); PW(0, 2, v.x, v.y)
            v = up2(ar2); PW(0, 4, v.x, v.y)
            v = up2(ar3); PW(0, 6, v.x, v.y)
            v = up2(az0); PW(1, 0, v.x, v.y)
            v = up2(az1); PW(1, 2, v.x, v.y)
            v = up2(az2); PW(1, 4, v.x, v.y)
            v = up2(az3); PW(1, 6, v.x, v.y)
            v = up2(an0); PW(2, 0, v.x, v.y)
            v = up2(an1); PW(2, 2, v.x, v.y)
            v = up2(an2); PW(2, 4, v.x, v.y)
            v = up2(an3); PW(2, 6, v.x, v.y)
#undef PW
        }

        // split barrier: producer-only warps arrive and move on; reducers sync.
        if (tid < 256) {
            asm volatile("bar.sync 1, 512;" ::: "memory");

            // ---- reduce over 16 k-splits; thread = (rlb, rhc) ----
            float sr = 0.f, sz = 0.f, sn = 0.f;
#pragma unroll
            for (int k2 = 0; k2 < 16; ++k2) {
                const float* pp = part + (k2 * 8 + rlb) * PART_STRIDE + rhc;
                sr += pp[0]; sz += pp[32]; sn += pp[64];
            }
            const float ghr = sr + bhr;
            const float ghz = sz + bhz;
            const float ghn = sn + bhn;
            const float r = sigm_fast(gxr + ghr);
            const float z = sigm_fast(gxz + ghz);
            const float n = tanh_fast(gxn + r * ghn);
            const float hprev = hbuf[cur * 2048 + rank * 256 + tid];
            const float hnew  = (1.f - z) * n + z * hprev;
            const float ho    = mv * hnew + (1.f - mv) * hprev;

            // broadcast first (critical path), then global store
            if (t + 1 < NS) {
                const int nxt = cur ^ 1;
                const unsigned c_data = HB_OFF_B + (unsigned)nxt * 8192u + slot_off;
                const unsigned c_bar  = BAR_OFF_B + (unsigned)nxt * 8u;
                const unsigned hv = __float_as_uint(ho);
#pragma unroll
                for (int r2 = 0; r2 < 8; ++r2)
                    st_async_tx(rbase[r2] + c_data, hv, rbase[r2] + c_bar);
            }
            out[obase] = ho;
        } else {
            asm volatile("bar.arrive 1, 512;" ::: "memory");
        }

        gxbase += G3;
        obase  += NH;
    }
}

extern "C" void kernel_launch(void* const* d_in, const int* in_sizes, int n_in,
                              void* d_out, int out_size) {
    const float* x    = (const float*)d_in[0];   // [B,S,D]
    const float* mask = (const float*)d_in[1];   // [B,S]
    const float* Wih  = (const float*)d_in[2];   // [D,3H]
    const float* Whh  = (const float*)d_in[3];   // [H,3H]
    const float* bih  = (const float*)d_in[4];   // [3H]
    const float* bhh  = (const float*)d_in[5];   // [3H]
    float* out = (float*)d_out;                  // [B,S,H]

    (void)in_sizes; (void)n_in; (void)out_size;

    // Phase 1: input projection GEMM
    dim3 g1(G3 / 128, (NB * NS) / 128);          // (6, 1024)
    gru_gemm1<<<g1, 256>>>(x, Wih, bih);

    // Phase 2: clustered recurrence
    cudaFuncSetAttribute(gru_rec, cudaFuncAttributeMaxDynamicSharedMemorySize,
                         SMEM2_BYTES);
    gru_rec<<<128, 512, SMEM2_BYTES>>>(mask, Whh, bhh, out);
}

// round 15
// speedup vs baseline: 1.5861x; 1.5861x over previous
#include <cuda_runtime.h>
#include <cuda_bf16.h>
#include <cstdint>
#include <cstddef>

typedef unsigned long long u64;

// Problem shape (fixed): B=128, S=1024, D=256, H=256
#define NB 128
#define NS 1024
#define NDIM 256
#define NH 256
#define G3 768              // 3*H

// gx scratch: [b][t][gate*256+h]  (402 MB, static device allocation — allowed)
__device__ float g_gx[(size_t)NB * NS * G3];

// ---------------- f32x2 helpers (sm_103a packed fp32) ----------------
__device__ __forceinline__ u64 pk2(float x, float y) {
    u64 r; asm("mov.b64 %0, {%1, %2};" : "=l"(r) : "f"(x), "f"(y)); return r;
}
__device__ __forceinline__ float2 up2(u64 a) {
    float2 r; asm("mov.b64 {%0, %1}, %2;" : "=f"(r.x), "=f"(r.y) : "l"(a)); return r;
}
__device__ __forceinline__ u64 ffma2(u64 a, u64 b, u64 c) {
    u64 d; asm("fma.rn.f32x2 %0, %1, %2, %3;" : "=l"(d) : "l"(a), "l"(b), "l"(c)); return d;
}
__device__ __forceinline__ float tanh_fast(float x) {
    float r; asm("tanh.approx.f32 %0, %1;" : "=f"(r) : "f"(x)); return r;
}
__device__ __forceinline__ float sigm_fast(float x) {
    // sigmoid(x) = 0.5 * tanh(x/2) + 0.5
    return fmaf(0.5f, tanh_fast(0.5f * x), 0.5f);
}

__device__ __forceinline__ unsigned smem_u32(const void* p) {
    unsigned a;
    asm("{ .reg .u64 t; cvta.to.shared.u64 t, %1; cvt.u32.u64 %0, t; }" : "=r"(a) : "l"(p));
    return a;
}
__device__ __forceinline__ unsigned mapa_rank(unsigned local, int rank) {
    unsigned r;
    asm("mapa.shared::cluster.u32 %0, %1, %2;" : "=r"(r) : "r"(local), "r"(rank));
    return r;
}
#define CLUSTER_SYNC() do { \
    asm volatile("barrier.cluster.arrive.aligned;" ::: "memory"); \
    asm volatile("barrier.cluster.wait.aligned;"   ::: "memory"); \
} while (0)

__device__ __forceinline__ void mbar_init(unsigned addr, unsigned cnt) {
    asm volatile("mbarrier.init.shared.b64 [%0], %1;" :: "r"(addr), "r"(cnt) : "memory");
}
__device__ __forceinline__ void mbar_expect_tx(unsigned addr, unsigned bytes) {
    asm volatile("mbarrier.arrive.expect_tx.shared.b64 _, [%0], %1;"
                 :: "r"(addr), "r"(bytes) : "memory");
}
__device__ __forceinline__ void mbar_wait(unsigned addr, unsigned parity) {
    asm volatile(
        "{\n\t"
        ".reg .pred P;\n\t"
        "WAIT_%=:\n\t"
        "mbarrier.try_wait.parity.acquire.cta.shared::cta.b64 P, [%0], %1, 0x989680;\n\t"
        "@P bra DONE_%=;\n\t"
        "bra WAIT_%=;\n\t"
        "DONE_%=:\n\t"
        "}"
        :: "r"(addr), "r"(parity) : "memory");
}
// remote smem store that completes tx on the remote CTA's mbarrier
__device__ __forceinline__ void st_async_tx(unsigned dst, unsigned val, unsigned rbar) {
    asm volatile(
        "st.async.weak.shared::cluster.mbarrier::complete_tx::bytes.b32 [%0], %1, [%2];"
        :: "r"(dst), "r"(val), "r"(rbar) : "memory");
}

// =====================================================================
// Phase 1: g_gx[m][n] = X[m][:] @ W_ih[:, n] + b_ih[n]
//   M = 131072 (m = b*1024 + t), K = 256, N = 768 (n = gate*256 + h)
// CTA tile 128x128, 256 threads, 8x8 per thread, f32x2 FMAs, KB=16.
// =====================================================================
#define KB1 16

__global__ void __launch_bounds__(256, 2)
gru_gemm1(const float* __restrict__ X, const float* __restrict__ W,
          const float* __restrict__ bias)
{
    __shared__ float As[KB1][132];   // [k][m], padded
    __shared__ float Bs[KB1][128];   // [k][n]

    const int tid   = threadIdx.x;
    const int mBase = blockIdx.y << 7;
    const int nBase = blockIdx.x << 7;
    const int tn = tid & 15;         // n sub-tile: tn*8
    const int tm = tid >> 4;         // m sub-tile: tm*8

    const int ar0 = tid >> 2;
    const int ac0 = (tid & 3) << 2;
    const int bk0 = tid >> 5;
    const int bn0 = (tid & 31) << 2;

    const float* Aptr = X + (size_t)(mBase + ar0) * NDIM + ac0;
    const float* Bptr = W + (size_t)bk0 * G3 + nBase + bn0;

    u64 acc[8][4];
#pragma unroll
    for (int i = 0; i < 8; ++i)
#pragma unroll
        for (int j = 0; j < 4; ++j) acc[i][j] = 0ull;

    float4 a0 = *(const float4*)(Aptr);
    float4 a1 = *(const float4*)(Aptr + 64 * NDIM);
    float4 b0 = *(const float4*)(Bptr);
    float4 b1 = *(const float4*)(Bptr + 8 * G3);

    for (int kc = 0; kc < NDIM; kc += KB1) {
        As[ac0 + 0][ar0] = a0.x; As[ac0 + 1][ar0] = a0.y;
        As[ac0 + 2][ar0] = a0.z; As[ac0 + 3][ar0] = a0.w;
        As[ac0 + 0][ar0 + 64] = a1.x; As[ac0 + 1][ar0 + 64] = a1.y;
        As[ac0 + 2][ar0 + 64] = a1.z; As[ac0 + 3][ar0 + 64] = a1.w;
        *(float4*)&Bs[bk0][bn0]     = b0;
        *(float4*)&Bs[bk0 + 8][bn0] = b1;
        __syncthreads();

        if (kc + KB1 < NDIM) {
            a0 = *(const float4*)(Aptr + (kc + KB1));
            a1 = *(const float4*)(Aptr + (kc + KB1) + 64 * NDIM);
            b0 = *(const float4*)(Bptr + (size_t)(kc + KB1) * G3);
            b1 = *(const float4*)(Bptr + (size_t)(kc + KB1 + 8) * G3);
        }

#pragma unroll
        for (int kk = 0; kk < KB1; ++kk) {
            float4 aA = *(const float4*)&As[kk][tm * 8];
            float4 aB = *(const float4*)&As[kk][tm * 8 + 4];
            u64 bp0 = *(const u64*)&Bs[kk][tn * 8 + 0];
            u64 bp1 = *(const u64*)&Bs[kk][tn * 8 + 2];
            u64 bp2 = *(const u64*)&Bs[kk][tn * 8 + 4];
            u64 bp3 = *(const u64*)&Bs[kk][tn * 8 + 6];
            u64 ad[8];
            ad[0] = pk2(aA.x, aA.x); ad[1] = pk2(aA.y, aA.y);
            ad[2] = pk2(aA.z, aA.z); ad[3] = pk2(aA.w, aA.w);
            ad[4] = pk2(aB.x, aB.x); ad[5] = pk2(aB.y, aB.y);
            ad[6] = pk2(aB.z, aB.z); ad[7] = pk2(aB.w, aB.w);
#pragma unroll
            for (int i = 0; i < 8; ++i) {
                acc[i][0] = ffma2(ad[i], bp0, acc[i][0]);
                acc[i][1] = ffma2(ad[i], bp1, acc[i][1]);
                acc[i][2] = ffma2(ad[i], bp2, acc[i][2]);
                acc[i][3] = ffma2(ad[i], bp3, acc[i][3]);
            }
        }
        __syncthreads();
    }

    float bb[8];
#pragma unroll
    for (int j = 0; j < 8; ++j) bb[j] = __ldg(bias + nBase + tn * 8 + j);

#pragma unroll
    for (int i = 0; i < 8; ++i) {
        size_t row = (size_t)(mBase + tm * 8 + i);
        float* o = g_gx + row * G3 + nBase + tn * 8;
        float2 p0 = up2(acc[i][0]), p1 = up2(acc[i][1]);
        float2 p2 = up2(acc[i][2]), p3 = up2(acc[i][3]);
        float4 lo = make_float4(p0.x + bb[0], p0.y + bb[1], p1.x + bb[2], p1.y + bb[3]);
        float4 hi = make_float4(p2.x + bb[4], p2.y + bb[5], p3.x + bb[6], p3.y + bb[7]);
        *(float4*)(o)     = lo;
        *(float4*)(o + 4) = hi;
    }
}

// =====================================================================
// Phase 2: GRU recurrence. 16 clusters x 8 CTAs; cluster = 8 batches;
// CTA = 32 hidden columns. 512 threads (16-way k-split).
// W_hh gates r,z in REGISTERS (32 floats/thread); gate n from smem
// with conflict-free [k][hc] layout (1 wavefront per LDS.32).
// Smem: Wn[256][32] 32KB | hbuf[2][256][8] 16KB | part[16*8][100] 50KB | mbar[2]
// =====================================================================
#define WN_FLOATS   (256 * 32)              // 8192
#define HB_FLOATS   (2 * 256 * 8)           // 4096
#define PART_STRIDE 100                     // 3*32 + 4 pad (bank spread)
#define PART_FLOATS (16 * 8 * PART_STRIDE)  // 12800
#define HB_OFF      WN_FLOATS
#define PART_OFF    (WN_FLOATS + HB_FLOATS)
#define HB_OFF_B    (WN_FLOATS * 4)                                  // 32768
#define BAR_OFF_B   ((WN_FLOATS + HB_FLOATS + PART_FLOATS) * 4)      // 100352
#define SMEM2_BYTES (BAR_OFF_B + 16)
#define TX_BYTES    8192u                   // 8 CTAs x 256 floats x 4B per step

__global__ void __launch_bounds__(512, 1) __cluster_dims__(8, 1, 1)
gru_rec(const float* __restrict__ mask, const float* __restrict__ Whh,
        const float* __restrict__ bhh, float* __restrict__ out)
{
    extern __shared__ float smem[];
    float* Wn   = smem;                  // [k][hc]
    float* hbuf = smem + HB_OFF;         // [buf][k][lb]  (k = global h index)
    float* part = smem + PART_OFF;       // [(ks*8+lb)*100 + g*32 + hc]

    const int tid  = threadIdx.x;
    const int rank = blockIdx.x & 7;
    const int cid  = blockIdx.x >> 3;
    const int hc   = tid & 31;                  // k-loop lane role
    const int ks   = tid >> 5;                  // 0..15 (k-split warp)
    const int hcg  = rank * 32 + hc;
    // reduce-phase remap (tid < 256): lb fast, hc slow -> coalesced broadcast
    const int rlb  = tid & 7;
    const int rhc  = (tid >> 3) & 31;
    const int rhcg = rank * 32 + rhc;

    // ---- W_hh gates r,z into REGISTERS (16 k each) ----
    float wrg[16], wzg[16];
    {
        const float* wb = Whh + (size_t)(ks * 16) * G3 + hcg;
#pragma unroll
        for (int j = 0; j < 16; ++j) {
            wrg[j] = __ldg(wb + (size_t)j * G3 + 0);
            wzg[j] = __ldg(wb + (size_t)j * G3 + 256);
        }
    }
    // ---- gate n into smem, [k][hc] conflict-free layout ----
    for (int idx = tid; idx < WN_FLOATS; idx += 512) {
        int k  = idx >> 5;
        int h2 = idx & 31;
        Wn[idx] = __ldg(Whh + (size_t)k * G3 + 512 + rank * 32 + h2);
    }
    for (int idx = tid; idx < HB_FLOATS; idx += 512) hbuf[HB_OFF * 0 + idx] = 0.f;

    const unsigned smem_base = smem_u32(smem);
    const unsigned barL0 = smem_base + BAR_OFF_B;
    const unsigned barL1 = smem_base + BAR_OFF_B + 8;
    if (tid == 0) {
        mbar_init(barL0, 1);
        mbar_init(barL1, 1);
        mbar_expect_tx(barL0, TX_BYTES);
        mbar_expect_tx(barL1, TX_BYTES);
    }

    const float bhr = __ldg(bhh + 0 * 256 + rhcg);
    const float bhz = __ldg(bhh + 1 * 256 + rhcg);
    const float bhn = __ldg(bhh + 2 * 256 + rhcg);

    // this thread's h slot byte offset (same in every rank's hbuf): rank*256 + tid
    const unsigned slot_off = (unsigned)((rank * 256 + tid) * 4);

    const int b_glob = cid * 8 + rlb;
    size_t gxbase = (size_t)b_glob * NS * G3 + rhcg;
    size_t obase  = (size_t)b_glob * NS * NH + rhcg;
    size_t mbase  = (size_t)b_glob * NS;

    const float* wnp = Wn + ks * 16 * 32 + hc;     // this warp's Wn base, stride 32
    __syncthreads();
    CLUSTER_SYNC();   // barriers + zeroed hbuf visible cluster-wide

    unsigned p0 = 0, p1 = 0;   // per-buffer wait parity

    for (int t = 0; t < NS; ++t) {
        const int cur = t & 1;

        // prefetch gx + mask BEFORE the wait (independent of h)
        float gxr = 0.f, gxz = 0.f, gxn = 0.f, mv = 0.f;
        if (tid < 256) {
            gxr = __ldg(g_gx + gxbase + 0);
            gxz = __ldg(g_gx + gxbase + 256);
            gxn = __ldg(g_gx + gxbase + 512);
            mv  = __ldg(mask + mbase + t);
        }

        if (t > 0) {
            if (cur == 0) { mbar_wait(barL0, p0); p0 ^= 1; }
            else          { mbar_wait(barL1, p1); p1 ^= 1; }
            if (tid == 0 && t + 2 < NS)
                mbar_expect_tx(cur ? barL1 : barL0, TX_BYTES);
        }

        // ---- gh partial: 16 k x 8 batches x 3 gates; r,z W in regs ----
        const float* hp = hbuf + cur * 2048 + ks * 128;
        u64 ar0 = 0, ar1 = 0, ar2 = 0, ar3 = 0;
        u64 az0 = 0, az1 = 0, az2 = 0, az3 = 0;
        u64 an0 = 0, an1 = 0, an2 = 0, an3 = 0;
#pragma unroll
        for (int kk = 0; kk < 16; ++kk) {
            ulonglong2 q0 = *(const ulonglong2*)(hp + kk * 8);
            ulonglong2 q1 = *(const ulonglong2*)(hp + kk * 8 + 4);
            float wn_s = wnp[kk * 32];
            u64 wr = pk2(wrg[kk], wrg[kk]);
            u64 wz = pk2(wzg[kk], wzg[kk]);
            u64 wn = pk2(wn_s, wn_s);
            ar0 = ffma2(wr, q0.x, ar0); ar1 = ffma2(wr, q0.y, ar1);
            ar2 = ffma2(wr, q1.x, ar2); ar3 = ffma2(wr, q1.y, ar3);
            az0 = ffma2(wz, q0.x, az0); az1 = ffma2(wz, q0.y, az1);
            az2 = ffma2(wz, q1.x, az2); az3 = ffma2(wz, q1.y, az3);
            an0 = ffma2(wn, q0.x, an0); an1 = ffma2(wn, q0.y, an1);
            an2 = ffma2(wn, q1.x, an2); an3 = ffma2(wn, q1.y, an3);
        }
        {
            float2 v;
            float* pb = part + ks * 8 * PART_STRIDE + hc;
#define PW(G, LB0, V0, V1) \
            pb[(LB0) * PART_STRIDE + (G) * 32] = (V0); \
            pb[((LB0) + 1) * PART_STRIDE + (G) * 32] = (V1);
            v = up2(ar0); PW(0, 0, v.x, v.y)
            v = up2(ar1); PW(0, 2, v.x, v.y)
            v = up2(ar2); PW(0, 4, v.x, v.y)
            v = up2(ar3); PW(0, 6, v.x, v.y)
            v = up2(az0); PW(1, 0, v.x, v.y)
            v = up2(az1); PW(1, 2, v.x, v.y)
            v = up2(az2); PW(1, 4, v.x, v.y)
            v = up2(az3); PW(1, 6, v.x, v.y)
            v = up2(an0); PW(2, 0, v.x, v.y)
            v = up2(an1); PW(2, 2, v.x, v.y)
            v = up2(an2); PW(2, 4, v.x, v.y)
            v = up2(an3); PW(2, 6, v.x, v.y)
#undef PW
        }

        // split barrier: producer-only warps arrive and move on; reducers sync.
        if (tid < 256) {
            asm volatile("bar.sync 1, 512;" ::: "memory");

            // ---- reduce over 16 k-splits; thread = (rlb, rhc) ----
            float sr = 0.f, sz = 0.f, sn = 0.f;
#pragma unroll
            for (int k2 = 0; k2 < 16; ++k2) {
                const float* pp = part + (k2 * 8 + rlb) * PART_STRIDE + rhc;
                sr += pp[0]; sz += pp[32]; sn += pp[64];
            }
            const float ghr = sr + bhr;
            const float ghz = sz + bhz;
            const float ghn = sn + bhn;
            const float r = sigm_fast(gxr + ghr);
            const float z = sigm_fast(gxz + ghz);
            const float n = tanh_fast(gxn + r * ghn);
            const float hprev = hbuf[cur * 2048 + rank * 256 + tid];
            const float hnew  = (1.f - z) * n + z * hprev;
            const float ho    = mv * hnew + (1.f - mv) * hprev;

            // broadcast first (critical path), then global store
            if (t + 1 < NS) {
                const int nxt = cur ^ 1;
                const unsigned c_data = HB_OFF_B + (unsigned)nxt * 8192u + slot_off;
                const unsigned c_bar  = BAR_OFF_B + (unsigned)nxt * 8u;
                const unsigned hv = __float_as_uint(ho);
#pragma unroll
                for (int r2 = 0; r2 < 8; ++r2) {
                    unsigned rb = mapa_rank(smem_base, r2);
                    st_async_tx(rb + c_data, hv, rb + c_bar);
                }
            }
            out[obase] = ho;
        } else {
            asm volatile("bar.arrive 1, 512;" ::: "memory");
        }

        gxbase += G3;
        obase  += NH;
    }
}

extern "C" void kernel_launch(void* const* d_in, const int* in_sizes, int n_in,
                              void* d_out, int out_size) {
    const float* x    = (const float*)d_in[0];   // [B,S,D]
    const float* mask = (const float*)d_in[1];   // [B,S]
    const float* Wih  = (const float*)d_in[2];   // [D,3H]
    const float* Whh  = (const float*)d_in[3];   // [H,3H]
    const float* bih  = (const float*)d_in[4];   // [3H]
    const float* bhh  = (const float*)d_in[5];   // [3H]
    float* out = (float*)d_out;                  // [B,S,H]

    (void)in_sizes; (void)n_in; (void)out_size;

    // Phase 1: input projection GEMM
    dim3 g1(G3 / 128, (NB * NS) / 128);          // (6, 1024)
    gru_gemm1<<<g1, 256>>>(x, Wih, bih);

    // Phase 2: clustered recurrence
    cudaFuncSetAttribute(gru_rec, cudaFuncAttributeMaxDynamicSharedMemorySize,
                         SMEM2_BYTES);
    gru_rec<<<128, 512, SMEM2_BYTES>>>(mask, Whh, bhh, out);
}